// round 4
// baseline (speedup 1.0000x reference)
#include <cuda_runtime.h>
#include <math.h>

#define NN 65536
#define EE 1048576
#define GG 32
#define SS 2048
#define FF 128
#define HH 128
#define CC 40
#define LL 3

// ---------------- scratch (device globals: no allocation allowed) ----------
__device__ float g_h[(size_t)NN * HH];      // 32 MB
__device__ float g_hw[(size_t)NN * HH];     // 32 MB
__device__ float g_wdyn[GG * FF * HH];      // 2 MB
__device__ int   g_deg[NN];
__device__ int   g_fill[NN];
__device__ float g_dinv[NN];
__device__ int   g_rowptr[NN + 1];
__device__ int   g_csrc[EE];                // 4 MB
__device__ int   g_is64;

// ---------------- init: zero counters, assume int64 until disproven --------
__global__ void init_kernel() {
    int n = blockIdx.x * 256 + threadIdx.x;
    if (n < NN) { g_deg[n] = 0; g_fill[n] = 0; }
    if (n == 0) g_is64 = 1;
}

// Detect whether edge_index is int64 or int32. If int64 (values < 2^31),
// every odd 32-bit word is zero. If int32, odd words are random node ids.
__global__ void detect_kernel(const unsigned* __restrict__ w) {
    int t = threadIdx.x;
    int bad = 0;
    for (int i = t; i < 4096; i += 256)
        if (w[2 * i + 1] != 0u) bad = 1;
    if (__syncthreads_or(bad)) {
        if (t == 0) g_is64 = 0;
    }
}

// ---------------- dynamic per-partition weights ----------------------------
// Wdyn[g,f,h] = relu(w0[f] * E_meta[g,h] + b0[f,h])
__global__ void wdyn_kernel(const float* __restrict__ w0,
                            const float* __restrict__ b0,
                            const float* __restrict__ emeta) {
    int idx = blockIdx.x * 256 + threadIdx.x;   // < 32*16384
    int g = idx >> 14;
    int rem = idx & 16383;
    int f = rem >> 7;
    int hh = rem & 127;
    float v = w0[f] * emeta[(g << 7) + hh] + b0[rem];
    g_wdyn[idx] = fmaxf(v, 0.0f);
}

// ---------------- CSR build ------------------------------------------------
__global__ void count_kernel(const void* __restrict__ ei) {
    int e = blockIdx.x * 256 + threadIdx.x;
    int d;
    if (g_is64) d = (int)((const long long*)ei)[(size_t)EE + e];
    else        d = ((const int*)ei)[(size_t)EE + e];
    atomicAdd(&g_deg[d], 1);
}

__global__ void dinv_kernel() {
    int n = blockIdx.x * 256 + threadIdx.x;
    g_dinv[n] = rsqrtf((float)(g_deg[n] + 1));   // +1 for self loop
}

// single-block exclusive scan of g_deg -> g_rowptr (65536 = 1024 threads x 64)
__global__ void scan_kernel() {
    const int t = threadIdx.x;
    const int base = t * 64;
    int s = 0;
    #pragma unroll 8
    for (int i = 0; i < 64; i++) s += g_deg[base + i];
    const int lane = t & 31, wid = t >> 5;
    const unsigned full = 0xffffffffu;
    int v = s;
    #pragma unroll
    for (int o = 1; o < 32; o <<= 1) {
        int u = __shfl_up_sync(full, v, o);
        if (lane >= o) v += u;
    }
    __shared__ int wsum[32];
    if (lane == 31) wsum[wid] = v;
    __syncthreads();
    if (wid == 0) {
        int w = wsum[lane];
        #pragma unroll
        for (int o = 1; o < 32; o <<= 1) {
            int u = __shfl_up_sync(full, w, o);
            if (lane >= o) w += u;
        }
        wsum[lane] = w;
    }
    __syncthreads();
    int off = v - s;                 // exclusive within warp
    if (wid > 0) off += wsum[wid - 1];
    int run = off;
    for (int i = 0; i < 64; i++) {
        g_rowptr[base + i] = run;
        run += g_deg[base + i];
    }
    if (t == 1023) g_rowptr[NN] = run;
}

__global__ void fill_kernel(const void* __restrict__ ei) {
    int e = blockIdx.x * 256 + threadIdx.x;
    int s, d;
    if (g_is64) {
        s = (int)((const long long*)ei)[e];
        d = (int)((const long long*)ei)[(size_t)EE + e];
    } else {
        s = ((const int*)ei)[e];
        d = ((const int*)ei)[(size_t)EE + e];
    }
    int p = atomicAdd(&g_fill[d], 1);
    g_csrc[g_rowptr[d] + p] = s;
}

// ---------------- GEMM: C[64x128 tile] = A[64x128] @ W[128x128] ------------
// seg != 0: W indexed per 2048-row partition (layer-0 dynamic weights).
#define GEMM_SMEM (128 * 128 * 4 + 64 * 132 * 4)
__global__ void gemm_kernel(const float* __restrict__ A,
                            const float* __restrict__ Wbase,
                            float* __restrict__ C, int seg) {
    extern __shared__ float sm[];
    float* Wsm = sm;                 // [128][128]
    float* Asm = sm + 128 * 128;     // [64][132] padded
    const int tid = threadIdx.x;
    const int rowbase = blockIdx.x * 64;
    const float* W = seg ? (Wbase + (size_t)(rowbase >> 11) * (128 * 128)) : Wbase;

    {   // load W (128x128 floats = 4096 float4)
        const float4* W4 = (const float4*)W;
        float4* Wsm4 = (float4*)Wsm;
        #pragma unroll
        for (int i = 0; i < 16; i++) Wsm4[tid + i * 256] = W4[tid + i * 256];
    }
    {   // load A tile (64x128 floats = 2048 float4), padded rows of 132
        const float4* A4 = (const float4*)(A + (size_t)rowbase * 128);
        #pragma unroll
        for (int j = 0; j < 8; j++) {
            int idx = tid + j * 256;
            int row = idx >> 5;
            int c4 = idx & 31;
            float4 v = A4[idx];
            *(float4*)&Asm[row * 132 + c4 * 4] = v;
        }
    }
    __syncthreads();

    const int tc = tid & 31;   // cols tc*4 .. tc*4+3
    const int tr = tid >> 5;   // rows tr*8 .. tr*8+7
    float4 acc[8];
    #pragma unroll
    for (int r = 0; r < 8; r++) acc[r] = make_float4(0.f, 0.f, 0.f, 0.f);

    #pragma unroll 4
    for (int k = 0; k < 128; k++) {
        float4 w4 = *(const float4*)&Wsm[k * 128 + tc * 4];
        #pragma unroll
        for (int r = 0; r < 8; r++) {
            float a = Asm[(tr * 8 + r) * 132 + k];   // uniform within warp
            acc[r].x += a * w4.x;
            acc[r].y += a * w4.y;
            acc[r].z += a * w4.z;
            acc[r].w += a * w4.w;
        }
    }
    #pragma unroll
    for (int r = 0; r < 8; r++)
        *(float4*)&C[(size_t)(rowbase + tr * 8 + r) * 128 + tc * 4] = acc[r];
}

// ---------------- aggregation: h = relu(D^-1/2 (A+I) D^-1/2 hw + b) --------
// one warp per node; each lane owns 4 contiguous columns (float4).
__global__ void agg_kernel(const float* __restrict__ hw,
                           const float* __restrict__ bias,
                           float* __restrict__ hout) {
    const int warp = threadIdx.x >> 5, lane = threadIdx.x & 31;
    const int n = blockIdx.x * 8 + warp;
    const float din = g_dinv[n];
    const float4* hw4 = (const float4*)hw;

    float4 acc;
    {   // self loop
        float4 v = hw4[(size_t)n * 32 + lane];
        float c = din * din;
        acc.x = v.x * c; acc.y = v.y * c; acc.z = v.z * c; acc.w = v.w * c;
    }
    const int beg = g_rowptr[n], end = g_rowptr[n + 1];
    for (int base = beg; base < end; base += 32) {
        int cnt = min(32, end - base);
        int s = 0; float ds = 0.f;
        if (lane < cnt) { s = g_csrc[base + lane]; ds = g_dinv[s]; }
        for (int i = 0; i < cnt; i++) {
            int   si = __shfl_sync(0xffffffffu, s, i);
            float c  = __shfl_sync(0xffffffffu, ds, i) * din;
            float4 v = hw4[(size_t)si * 32 + lane];
            acc.x += v.x * c; acc.y += v.y * c; acc.z += v.z * c; acc.w += v.w * c;
        }
    }
    float4 b = *(const float4*)&bias[lane * 4];
    acc.x = fmaxf(acc.x + b.x, 0.f);
    acc.y = fmaxf(acc.y + b.y, 0.f);
    acc.z = fmaxf(acc.z + b.z, 0.f);
    acc.w = fmaxf(acc.w + b.w, 0.f);
    *(float4*)&hout[(size_t)n * 128 + lane * 4] = acc;
}

// ---------------- classifier + log_softmax ---------------------------------
// warp per node; lt1_w [40][128] staged in smem.
__global__ void cls_kernel(const float* __restrict__ h,
                           const float* __restrict__ w,
                           const float* __restrict__ b,
                           float* __restrict__ out) {
    __shared__ float wsm[CC * 128];
    __shared__ float bsm[CC];
    const int tid = threadIdx.x;
    for (int i = tid; i < CC * 128; i += 256) wsm[i] = w[i];
    if (tid < CC) bsm[tid] = b[tid];
    __syncthreads();

    const int warp = tid >> 5, lane = tid & 31;
    const int n = blockIdx.x * 8 + warp;
    float4 h4 = *(const float4*)&h[(size_t)n * 128 + lane * 4];

    float la = 0.f, lb = 0.f;
    #pragma unroll
    for (int c = 0; c < CC; c++) {
        float4 w4 = *(const float4*)&wsm[c * 128 + lane * 4];
        float p = h4.x * w4.x + h4.y * w4.y + h4.z * w4.z + h4.w * w4.w;
        #pragma unroll
        for (int o = 16; o > 0; o >>= 1) p += __shfl_xor_sync(0xffffffffu, p, o);
        p += bsm[c];
        if (c == lane)      la = p;
        if (c == 32 + lane) lb = p;
    }
    // max over 40 logits
    float m = la;
    if (lane < CC - 32) m = fmaxf(m, lb);
    #pragma unroll
    for (int o = 16; o > 0; o >>= 1) m = fmaxf(m, __shfl_xor_sync(0xffffffffu, m, o));
    // sum exp
    float s = expf(la - m) + ((lane < CC - 32) ? expf(lb - m) : 0.f);
    #pragma unroll
    for (int o = 16; o > 0; o >>= 1) s += __shfl_xor_sync(0xffffffffu, s, o);
    float ls = m + logf(s);
    out[(size_t)n * CC + lane] = la - ls;
    if (lane < CC - 32) out[(size_t)n * CC + 32 + lane] = lb - ls;
}

// ---------------- launch ---------------------------------------------------
extern "C" void kernel_launch(void* const* d_in, const int* in_sizes, int n_in,
                              void* d_out, int out_size) {
    const float* x     = (const float*)d_in[0];
    const void*  ei    = d_in[1];                  // [2,E] int64 or int32
    const float* emeta = (const float*)d_in[2];
    // d_in[3] = ptr (uniform partitions, unused)
    const float* w0    = (const float*)d_in[4];
    const float* b0    = (const float*)d_in[5];
    const float* convw = (const float*)d_in[6];
    const float* convb = (const float*)d_in[7];
    const float* ltw   = (const float*)d_in[8];
    const float* ltb   = (const float*)d_in[9];
    float* out = (float*)d_out;

    cudaFuncSetAttribute(gemm_kernel,
                         cudaFuncAttributeMaxDynamicSharedMemorySize, GEMM_SMEM);

    float *ph, *phw, *pwd;
    cudaGetSymbolAddress((void**)&ph,  g_h);
    cudaGetSymbolAddress((void**)&phw, g_hw);
    cudaGetSymbolAddress((void**)&pwd, g_wdyn);

    // ---- graph prep: degrees + CSR (reused across all layers) ----
    init_kernel<<<NN / 256, 256>>>();
    detect_kernel<<<1, 256>>>((const unsigned*)ei);
    wdyn_kernel<<<GG * FF * HH / 256, 256>>>(w0, b0, emeta);
    count_kernel<<<EE / 256, 256>>>(ei);
    dinv_kernel<<<NN / 256, 256>>>();
    scan_kernel<<<1, 1024>>>();
    fill_kernel<<<EE / 256, 256>>>(ei);

    // ---- h0 = segment_matmul(x, Wdyn) ----
    gemm_kernel<<<NN / 64, 256, GEMM_SMEM>>>(x, pwd, ph, 1);

    // ---- 3 GCN layers ----
    for (int l = 0; l < LL; l++) {
        gemm_kernel<<<NN / 64, 256, GEMM_SMEM>>>(ph, convw + (size_t)l * HH * HH, phw, 0);
        agg_kernel<<<NN / 8, 256>>>(phw, convb + (size_t)l * HH, ph);
    }

    // ---- classifier + log_softmax ----
    cls_kernel<<<NN / 8, 256>>>(ph, ltw, ltb, out);
}